// round 1
// baseline (speedup 1.0000x reference)
#include <cuda_runtime.h>
#include <cuda_bf16.h>
#include <math.h>

// ---------------- problem constants ----------------
#define Dm 1024      // d_model
#define Hd 4096      // expert hidden
#define Ex 8         // experts
#define TK 2         // top-k
#define Bb 4
#define Ss 2048
#define Tt (Bb * Ss)         // 8192 tokens
#define PAIRS (Tt * TK)      // 16384
#define CAP 2560             // ceil(1.25 * T * K / E)

// ---------------- device scratch (no allocations allowed) ----------------
__device__ float g_h[(size_t)Ex * CAP * Hd];    // expert hidden activations (335 MB)
__device__ float g_eo[(size_t)Ex * CAP * Dm];   // expert outputs (84 MB)
__device__ int   g_eid[PAIRS];                  // expert id per (token,k) pair
__device__ float g_wp[PAIRS];                   // gate weight per pair
__device__ int   g_slot[PAIRS];                 // dest slot per pair, -1 if dropped
__device__ int   g_tok[Ex * CAP];               // token index per slot
__device__ int   g_count[Ex];                   // kept rows per expert

// ---------------- router: warp per token ----------------
__global__ void router_kernel(const float* __restrict__ x,
                              const float* __restrict__ Wr)
{
    int warp = (blockIdx.x * blockDim.x + threadIdx.x) >> 5;
    int lane = threadIdx.x & 31;
    if (warp >= Tt) return;
    const float* xr = x + (size_t)warp * Dm;

    float acc[8];
#pragma unroll
    for (int e = 0; e < 8; e++) acc[e] = 0.f;

    for (int d = lane; d < Dm; d += 32) {
        float xv = __ldg(xr + d);
        const float4 a = *(const float4*)(Wr + d * 8);
        const float4 b = *(const float4*)(Wr + d * 8 + 4);
        acc[0] += xv * a.x; acc[1] += xv * a.y; acc[2] += xv * a.z; acc[3] += xv * a.w;
        acc[4] += xv * b.x; acc[5] += xv * b.y; acc[6] += xv * b.z; acc[7] += xv * b.w;
    }
#pragma unroll
    for (int e = 0; e < 8; e++) {
#pragma unroll
        for (int off = 16; off > 0; off >>= 1)
            acc[e] += __shfl_xor_sync(0xFFFFFFFFu, acc[e], off);
    }
    if (lane == 0) {
        // top-2 (first index wins ties, like jax top_k)
        int e0 = 0;
        float l0 = acc[0];
#pragma unroll
        for (int e = 1; e < 8; e++) if (acc[e] > l0) { l0 = acc[e]; e0 = e; }
        int e1 = -1;
        float l1 = -3.4e38f;
#pragma unroll
        for (int e = 0; e < 8; e++) {
            if (e == e0) continue;
            if (acc[e] > l1) { l1 = acc[e]; e1 = e; }
        }
        // renormalized softmax over top-2 == sigmoid of logit gap
        float w0 = 1.0f / (1.0f + __expf(l1 - l0));
        g_eid[2 * warp + 0] = e0;
        g_eid[2 * warp + 1] = e1;
        g_wp[2 * warp + 0] = w0;
        g_wp[2 * warp + 1] = 1.0f - w0;
    }
}

// ---------------- exact ordered capacity dispatch (single block) ----------------
__global__ void scan_kernel()
{
    __shared__ int sc[8][1024];   // 32 KB
    int tid = threadIdx.x;
    int base = tid * 16;

    int le[16];
    int lc[8];
#pragma unroll
    for (int e = 0; e < 8; e++) lc[e] = 0;
#pragma unroll
    for (int i = 0; i < 16; i++) {
        le[i] = g_eid[base + i];
        lc[le[i]]++;
    }
#pragma unroll
    for (int e = 0; e < 8; e++) sc[e][tid] = lc[e];
    __syncthreads();

    // Hillis-Steele inclusive scan across 1024 threads, 8 lanes
    for (int off = 1; off < 1024; off <<= 1) {
        int v[8];
#pragma unroll
        for (int e = 0; e < 8; e++) v[e] = (tid >= off) ? sc[e][tid - off] : 0;
        __syncthreads();
#pragma unroll
        for (int e = 0; e < 8; e++) sc[e][tid] += v[e];
        __syncthreads();
    }

    int pos[8];
#pragma unroll
    for (int e = 0; e < 8; e++) pos[e] = sc[e][tid] - lc[e];   // exclusive prefix

#pragma unroll
    for (int i = 0; i < 16; i++) {
        int e = le[i];
        int p = pos[e]++;
        int pr = base + i;
        if (p < CAP) {
            int slot = e * CAP + p;
            g_slot[pr] = slot;
            g_tok[slot] = pr >> 1;   // token index
        } else {
            g_slot[pr] = -1;         // dropped
        }
    }
    if (tid < 8) {
        int c = sc[tid][1023];
        g_count[tid] = (c < CAP) ? c : CAP;
    }
}

// ---------------- tanh-approx GELU (matches jax.nn.gelu default) ----------------
__device__ __forceinline__ float gelu_tanh(float v)
{
    float c = 0.7978845608028654f * (v + 0.044715f * v * v * v);
    return 0.5f * v * (1.0f + tanhf(c));
}

// ---------------- tiled expert SGEMM: C[slot] = act(A @ B[e] + bias[e]) ------
// GATHER=true:  A row = x[g_tok[slot]], C = g_h, act = GELU   (Kdim=1024, Ndim=4096)
// GATHER=false: A row = g_h[slot],      C = g_eo, act = id    (Kdim=4096, Ndim=1024)
template <int Kdim, int Ndim, bool GELU, bool GATHER>
__global__ __launch_bounds__(256, 2)
void expert_gemm(const float* __restrict__ Ax,
                 const float* __restrict__ Bw,
                 const float* __restrict__ bias)
{
    constexpr int BM = 128, BN = 128, BK = 16;
    constexpr int MT = CAP / BM;   // 20 row tiles / expert

    __shared__ float As[BK][BM + 4];
    __shared__ float Bs[BK][BN + 4];
    __shared__ int   srow[BM];

    int e  = blockIdx.y / MT;
    int m0 = (blockIdx.y % MT) * BM;
    int cnt = g_count[e];
    if (m0 >= cnt) return;

    int n0  = blockIdx.x * BN;
    int tid = threadIdx.x;

    const float* Asrc = GATHER ? Ax : g_h;

    if (tid < BM) {
        int r = m0 + tid;
        int gr;
        if (r < cnt) gr = GATHER ? g_tok[e * CAP + r] : (e * CAP + r);
        else         gr = GATHER ? 0 : (e * CAP);   // safe dummy row
        srow[tid] = gr;
    }
    __syncthreads();

    const float* Bexp = Bw + (size_t)e * Kdim * Ndim;

    float acc[8][8];
#pragma unroll
    for (int i = 0; i < 8; i++)
#pragma unroll
        for (int j = 0; j < 8; j++) acc[i][j] = 0.f;

    int ty = tid >> 4;     // 0..15 -> row group
    int tx = tid & 15;     // 0..15 -> col group

    for (int k0 = 0; k0 < Kdim; k0 += BK) {
        // A tile: 128 rows x 16 cols = 512 float4, 2 per thread (store transposed)
#pragma unroll
        for (int l = 0; l < 2; l++) {
            int f   = tid + l * 256;
            int row = f >> 2;
            int c4  = (f & 3) * 4;
            const float4 v = *(const float4*)(Asrc + (size_t)srow[row] * Kdim + k0 + c4);
            As[c4 + 0][row] = v.x;
            As[c4 + 1][row] = v.y;
            As[c4 + 2][row] = v.z;
            As[c4 + 3][row] = v.w;
        }
        // B tile: 16 rows x 128 cols = 512 float4, 2 per thread
#pragma unroll
        for (int l = 0; l < 2; l++) {
            int f   = tid + l * 256;
            int row = f >> 5;
            int c4  = (f & 31) * 4;
            *(float4*)&Bs[row][c4] =
                *(const float4*)(Bexp + (size_t)(k0 + row) * Ndim + n0 + c4);
        }
        __syncthreads();

#pragma unroll
        for (int k = 0; k < BK; k++) {
            float ra[8], rb[8];
#pragma unroll
            for (int i = 0; i < 8; i++) ra[i] = As[k][ty * 8 + i];
#pragma unroll
            for (int j = 0; j < 8; j++) rb[j] = Bs[k][tx * 8 + j];
#pragma unroll
            for (int i = 0; i < 8; i++)
#pragma unroll
                for (int j = 0; j < 8; j++) acc[i][j] += ra[i] * rb[j];
        }
        __syncthreads();
    }

    // epilogue
    const float* bv = bias + e * Ndim + n0;
    float* Cbase = GELU ? g_h : g_eo;
#pragma unroll
    for (int i = 0; i < 8; i++) {
        int r = m0 + ty * 8 + i;
        if (r >= cnt) continue;
        float* crow = Cbase + (size_t)(e * CAP + r) * Ndim + n0 + tx * 8;
        float v[8];
#pragma unroll
        for (int j = 0; j < 8; j++) {
            float t = acc[i][j] + bv[tx * 8 + j];
            v[j] = GELU ? gelu_tanh(t) : t;
        }
        *(float4*)(crow)     = make_float4(v[0], v[1], v[2], v[3]);
        *(float4*)(crow + 4) = make_float4(v[4], v[5], v[6], v[7]);
    }
}

// ---------------- combine: one block per token ----------------
__global__ void combine_kernel(float* __restrict__ out)
{
    int t = blockIdx.x;
    int c = threadIdx.x * 4;   // 256 threads * 4 = 1024 = Dm

    int   s0 = g_slot[2 * t + 0];
    int   s1 = g_slot[2 * t + 1];
    float w0 = g_wp[2 * t + 0];
    float w1 = g_wp[2 * t + 1];

    float4 r = make_float4(0.f, 0.f, 0.f, 0.f);
    if (s0 >= 0) {
        float4 a = *(const float4*)(g_eo + (size_t)s0 * Dm + c);
        r.x += w0 * a.x; r.y += w0 * a.y; r.z += w0 * a.z; r.w += w0 * a.w;
    }
    if (s1 >= 0) {
        float4 a = *(const float4*)(g_eo + (size_t)s1 * Dm + c);
        r.x += w1 * a.x; r.y += w1 * a.y; r.z += w1 * a.z; r.w += w1 * a.w;
    }
    *(float4*)(out + (size_t)t * Dm + c) = r;
}

// ---------------- entry point ----------------
extern "C" void kernel_launch(void* const* d_in, const int* in_sizes, int n_in,
                              void* d_out, int out_size)
{
    const float* x  = (const float*)d_in[0];   // [B,S,D]
    const float* Wr = (const float*)d_in[1];   // [D,E]
    const float* W1 = (const float*)d_in[2];   // [E,D,H]
    const float* b1 = (const float*)d_in[3];   // [E,H]
    const float* W2 = (const float*)d_in[4];   // [E,H,D]
    const float* b2 = (const float*)d_in[5];   // [E,D]
    float* out = (float*)d_out;

    // 1) router: 8 warps / block
    router_kernel<<<Tt / 8, 256>>>(x, Wr);

    // 2) exact ordered capacity dispatch
    scan_kernel<<<1, 1024>>>();

    // 3) GEMM1 + GELU: x[gather] @ W1 + b1 -> g_h   (M<=CAP per expert, N=4096, K=1024)
    {
        dim3 grid(Hd / 128, Ex * (CAP / 128));
        expert_gemm<Dm, Hd, true, true><<<grid, 256>>>(x, W1, b1);
    }

    // 4) GEMM2: g_h @ W2 + b2 -> g_eo               (N=1024, K=4096)
    {
        dim3 grid(Dm / 128, Ex * (CAP / 128));
        expert_gemm<Hd, Dm, false, false><<<grid, 256>>>(nullptr, W2, b2);
    }

    // 5) combine
    combine_kernel<<<Tt, 256>>>(out);
}

// round 4
// speedup vs baseline: 1.4133x; 1.4133x over previous
#include <cuda_runtime.h>
#include <cuda_bf16.h>
#include <mma.h>
#include <math.h>
#include <stdint.h>

using namespace nvcuda;

// ---------------- problem constants ----------------
#define Dm 1024      // d_model
#define Hd 4096      // expert hidden
#define Ex 8         // experts
#define TK 2         // top-k
#define Bb 4
#define Ss 2048
#define Tt (Bb * Ss)         // 8192 tokens
#define PAIRS (Tt * TK)      // 16384
#define CAP 2560             // ceil(1.25 * T * K / E)

// ---------------- device scratch (no allocations allowed) ----------------
__device__ float g_h  [(size_t)Ex * CAP * Hd];   // expert hidden activations
__device__ float g_eo [(size_t)Ex * CAP * Dm];   // expert outputs
__device__ int   g_eid[PAIRS];
__device__ float g_wp [PAIRS];
__device__ int   g_slot[PAIRS];
__device__ int   g_tok[Ex * CAP];
__device__ int   g_count[Ex];

// ---------------- cp.async helpers ----------------
__device__ __forceinline__ uint32_t smem_u32(const void* p) {
    uint32_t a;
    asm("{ .reg .u64 t; cvta.to.shared.u64 t, %1; cvt.u32.u64 %0, t; }" : "=r"(a) : "l"(p));
    return a;
}
__device__ __forceinline__ void cp16(uint32_t dst, const void* src) {
    asm volatile("cp.async.cg.shared.global [%0], [%1], 16;" :: "r"(dst), "l"(src));
}
#define CP_COMMIT() asm volatile("cp.async.commit_group;" ::: "memory")
#define CP_WAIT(n)  asm volatile("cp.async.wait_group %0;" :: "n"(n) : "memory")

// ---------------- router: warp per token ----------------
__global__ void router_kernel(const float* __restrict__ x,
                              const float* __restrict__ Wr)
{
    int warp = (blockIdx.x * blockDim.x + threadIdx.x) >> 5;
    int lane = threadIdx.x & 31;
    if (warp >= Tt) return;
    const float* xr = x + (size_t)warp * Dm;

    float acc[8];
#pragma unroll
    for (int e = 0; e < 8; e++) acc[e] = 0.f;
    for (int d = lane; d < Dm; d += 32) {
        float xv = __ldg(xr + d);
        const float4 a = *(const float4*)(Wr + d * 8);
        const float4 b = *(const float4*)(Wr + d * 8 + 4);
        acc[0] += xv * a.x; acc[1] += xv * a.y; acc[2] += xv * a.z; acc[3] += xv * a.w;
        acc[4] += xv * b.x; acc[5] += xv * b.y; acc[6] += xv * b.z; acc[7] += xv * b.w;
    }
#pragma unroll
    for (int e = 0; e < 8; e++)
#pragma unroll
        for (int off = 16; off > 0; off >>= 1)
            acc[e] += __shfl_xor_sync(0xFFFFFFFFu, acc[e], off);
    if (lane == 0) {
        int e0 = 0; float l0 = acc[0];
#pragma unroll
        for (int e = 1; e < 8; e++) if (acc[e] > l0) { l0 = acc[e]; e0 = e; }
        int e1 = -1; float l1 = -3.4e38f;
#pragma unroll
        for (int e = 0; e < 8; e++) {
            if (e == e0) continue;
            if (acc[e] > l1) { l1 = acc[e]; e1 = e; }
        }
        float w0 = 1.0f / (1.0f + __expf(l1 - l0));
        g_eid[2 * warp + 0] = e0;  g_eid[2 * warp + 1] = e1;
        g_wp [2 * warp + 0] = w0;  g_wp [2 * warp + 1] = 1.0f - w0;
    }
}

// ---------------- exact ordered capacity dispatch (single block) ----------------
__global__ void scan_kernel()
{
    __shared__ int sc[8][1024];
    int tid = threadIdx.x;
    int base = tid * 16;

    int le[16]; int lc[8];
#pragma unroll
    for (int e = 0; e < 8; e++) lc[e] = 0;
#pragma unroll
    for (int i = 0; i < 16; i++) { le[i] = g_eid[base + i]; lc[le[i]]++; }
#pragma unroll
    for (int e = 0; e < 8; e++) sc[e][tid] = lc[e];
    __syncthreads();
    for (int off = 1; off < 1024; off <<= 1) {
        int v[8];
#pragma unroll
        for (int e = 0; e < 8; e++) v[e] = (tid >= off) ? sc[e][tid - off] : 0;
        __syncthreads();
#pragma unroll
        for (int e = 0; e < 8; e++) sc[e][tid] += v[e];
        __syncthreads();
    }
    int pos[8];
#pragma unroll
    for (int e = 0; e < 8; e++) pos[e] = sc[e][tid] - lc[e];
#pragma unroll
    for (int i = 0; i < 16; i++) {
        int e = le[i]; int p = pos[e]++; int pr = base + i;
        if (p < CAP) { int s = e * CAP + p; g_slot[pr] = s; g_tok[s] = pr >> 1; }
        else g_slot[pr] = -1;
    }
    if (tid < 8) { int c = sc[tid][1023]; g_count[tid] = (c < CAP) ? c : CAP; }
}

// ---------------- GELU (tanh approx, matches jax.nn.gelu) ----------------
__device__ __forceinline__ float gelu_tanh(float v)
{
    float c = 0.7978845608028654f * (v + 0.044715f * v * v * v);
    return 0.5f * v * (1.0f + tanhf(c));
}

// ---------------- wmma tf32 expert GEMM ----------------
// C[128x128] = act( A @ B + bias ),  A:[M][K] row-major (gathered rows),
// B:[K][N] row-major = native weight layout (W1: [D][H], W2: [H][D]).
// 8 warps, warp tile 32(M) x 64(N); wmma 16x16x8 tf32; 2-stage cp.async.
template <int Kdim, int Ndim, bool GELU, bool GATHER>
__global__ void __launch_bounds__(256)
expert_wmma(const float* __restrict__ Ax,
            const float* __restrict__ Bw,
            const float* __restrict__ bias)
{
    constexpr int BM = 128, BN = 128, BK = 32;
    constexpr int MT = CAP / BM;              // 20 row tiles / expert
    constexpr int AST = BK + 8;               // A smem row stride (floats): 160B
    constexpr int BST = BN + 8;               // B smem row stride (floats): 544B
    constexpr int ABYTES = BM * AST * 4;      // 20480
    constexpr int BBYTES = BK * BST * 4;      // 17408
    constexpr int STAGE  = ABYTES + BBYTES;   // 37888
    constexpr int CST = BN + 4;               // C smem stride: 528B (16B-mult)

    extern __shared__ __align__(16) char smem[];
    int*   srow = (int*)smem;                          // 512 B
    float* sC   = (float*)(smem + 512);                // reused after mainloop
    char*  stg  = smem + 512;
    const uint32_t stg_u = smem_u32(stg);

    const int e   = blockIdx.y / MT;
    const int m0  = (blockIdx.y % MT) * BM;
    const int cnt = g_count[e];
    if (m0 >= cnt) return;
    const int n0  = blockIdx.x * BN;
    const int tid = threadIdx.x;
    const int wid = tid >> 5;

    // gather row table
    if (tid < BM) {
        int r = m0 + tid;
        srow[tid] = (r < cnt) ? (GATHER ? g_tok[e * CAP + r] : e * CAP + r)
                              : (GATHER ? 0 : e * CAP);
    }
    __syncthreads();

    const float* Asrc = GATHER ? Ax : (const float*)g_h;
    const float* Bexp = Bw + (size_t)e * Kdim * Ndim + n0;

    // A: 1024 16B chunks; chunk = tid + l*256 -> row=chunk/8, c16=chunk%8
    const int arow = tid >> 3, ac16 = tid & 7;
    size_t aoff[4];
#pragma unroll
    for (int l = 0; l < 4; l++)
        aoff[l] = (size_t)srow[arow + l * 32] * Kdim + ac16 * 4;
    // B: 1024 chunks; row=chunk/32, c16=chunk%32
    const int brow = tid >> 5, bc16 = tid & 31;

    auto load_stage = [&](int s, int k0) {
        uint32_t sA = stg_u + s * STAGE;
        uint32_t sB = sA + ABYTES;
#pragma unroll
        for (int l = 0; l < 4; l++) {
            int row = arow + l * 32;
            cp16(sA + (uint32_t)(row * (AST * 4) + ac16 * 16), Asrc + aoff[l] + k0);
        }
#pragma unroll
        for (int l = 0; l < 4; l++) {
            int row = brow + l * 8;
            cp16(sB + (uint32_t)(row * (BST * 4) + bc16 * 16),
                 Bexp + (size_t)(k0 + row) * Ndim + bc16 * 4);
        }
        CP_COMMIT();
    };

    // warp tiling: warp_m in [0,4), warp_n in [0,2)
    const int warp_m = wid >> 1;
    const int warp_n = wid & 1;

    wmma::fragment<wmma::accumulator, 16, 16, 8, float> acc[2][4];
#pragma unroll
    for (int i = 0; i < 2; i++)
#pragma unroll
        for (int j = 0; j < 4; j++) wmma::fill_fragment(acc[i][j], 0.f);

    constexpr int KT = Kdim / BK;
    load_stage(0, 0);

    for (int j = 0; j < KT; j++) {
        if (j + 1 < KT) { load_stage((j + 1) & 1, (j + 1) * BK); CP_WAIT(1); }
        else            { CP_WAIT(0); }
        __syncthreads();

        const float* sA = (const float*)(stg + (j & 1) * STAGE);
        const float* sB = (const float*)(stg + (j & 1) * STAGE + ABYTES);

#pragma unroll
        for (int ks = 0; ks < BK / 8; ks++) {
            wmma::fragment<wmma::matrix_a, 16, 16, 8, wmma::precision::tf32, wmma::row_major> af[2];
            wmma::fragment<wmma::matrix_b, 16, 16, 8, wmma::precision::tf32, wmma::row_major> bf[4];
#pragma unroll
            for (int i = 0; i < 2; i++) {
                wmma::load_matrix_sync(af[i], sA + (warp_m * 32 + i * 16) * AST + ks * 8, AST);
#pragma unroll
                for (int t = 0; t < af[i].num_elements; t++)
                    af[i].x[t] = wmma::__float_to_tf32(af[i].x[t]);
            }
#pragma unroll
            for (int jn = 0; jn < 4; jn++) {
                wmma::load_matrix_sync(bf[jn], sB + (ks * 8) * BST + warp_n * 64 + jn * 16, BST);
#pragma unroll
                for (int t = 0; t < bf[jn].num_elements; t++)
                    bf[jn].x[t] = wmma::__float_to_tf32(bf[jn].x[t]);
            }
#pragma unroll
            for (int i = 0; i < 2; i++)
#pragma unroll
                for (int jn = 0; jn < 4; jn++)
                    wmma::mma_sync(acc[i][jn], af[i], bf[jn], acc[i][jn]);
        }
        __syncthreads();
    }

    // dump accumulators to smem C
#pragma unroll
    for (int i = 0; i < 2; i++)
#pragma unroll
        for (int jn = 0; jn < 4; jn++)
            wmma::store_matrix_sync(sC + (warp_m * 32 + i * 16) * CST + warp_n * 64 + jn * 16,
                                    acc[i][jn], CST, wmma::mem_row_major);
    __syncthreads();

    // epilogue: 2 threads per row, 64 cols each
    {
        const int row  = tid >> 1;
        const int col0 = (tid & 1) * 64;
        const int r = m0 + row;
        if (r < cnt) {
            const float* bv = bias + e * Ndim + n0 + col0;
            float* crow = (GELU ? g_h : g_eo) + ((size_t)(e * CAP + r)) * Ndim + n0 + col0;
            const float* src = sC + row * CST + col0;
#pragma unroll
            for (int c = 0; c < 64; c += 4) {
                float4 v = *(const float4*)(src + c);
                v.x += __ldg(bv + c + 0);
                v.y += __ldg(bv + c + 1);
                v.z += __ldg(bv + c + 2);
                v.w += __ldg(bv + c + 3);
                if (GELU) {
                    v.x = gelu_tanh(v.x); v.y = gelu_tanh(v.y);
                    v.z = gelu_tanh(v.z); v.w = gelu_tanh(v.w);
                }
                *(float4*)(crow + c) = v;
            }
        }
    }
}

// ---------------- combine: one block per token ----------------
__global__ void combine_kernel(float* __restrict__ out)
{
    int t = blockIdx.x;
    int c = threadIdx.x * 4;
    int   s0 = g_slot[2 * t + 0];
    int   s1 = g_slot[2 * t + 1];
    float w0 = g_wp[2 * t + 0];
    float w1 = g_wp[2 * t + 1];
    float4 r = make_float4(0.f, 0.f, 0.f, 0.f);
    if (s0 >= 0) {
        float4 a = *(const float4*)(g_eo + (size_t)s0 * Dm + c);
        r.x += w0 * a.x; r.y += w0 * a.y; r.z += w0 * a.z; r.w += w0 * a.w;
    }
    if (s1 >= 0) {
        float4 a = *(const float4*)(g_eo + (size_t)s1 * Dm + c);
        r.x += w1 * a.x; r.y += w1 * a.y; r.z += w1 * a.z; r.w += w1 * a.w;
    }
    *(float4*)(out + (size_t)t * Dm + c) = r;
}

// ---------------- entry point ----------------
extern "C" void kernel_launch(void* const* d_in, const int* in_sizes, int n_in,
                              void* d_out, int out_size)
{
    const float* x  = (const float*)d_in[0];
    const float* Wr = (const float*)d_in[1];
    const float* W1 = (const float*)d_in[2];
    const float* b1 = (const float*)d_in[3];
    const float* W2 = (const float*)d_in[4];
    const float* b2 = (const float*)d_in[5];
    float* out = (float*)d_out;

    // dynamic smem: 512 (srow) + 2 stages of 37888 = 76288 bytes
    constexpr int SMEM_SZ = 512 + 2 * 37888;
    static_assert(512 + 128 * (128 + 4) * 4 <= SMEM_SZ, "C reuse fits");
    cudaFuncSetAttribute((const void*)&expert_wmma<Dm, Hd, true,  true >,
                         cudaFuncAttributeMaxDynamicSharedMemorySize, SMEM_SZ);
    cudaFuncSetAttribute((const void*)&expert_wmma<Hd, Dm, false, false>,
                         cudaFuncAttributeMaxDynamicSharedMemorySize, SMEM_SZ);

    // 1) router
    router_kernel<<<Tt / 8, 256>>>(x, Wr);
    // 2) exact ordered capacity dispatch
    scan_kernel<<<1, 1024>>>();
    // 3) GEMM1 + GELU: x[gather] @ W1 + b1 -> g_h   (K=1024, N=4096)
    expert_wmma<Dm, Hd, true,  true ><<<dim3(Hd / 128, Ex * (CAP / 128)), 256, SMEM_SZ>>>(x, W1, b1);
    // 4) GEMM2: g_h @ W2 + b2 -> g_eo               (K=4096, N=1024)
    expert_wmma<Hd, Dm, false, false><<<dim3(Dm / 128, Ex * (CAP / 128)), 256, SMEM_SZ>>>(nullptr, W2, b2);
    // 5) combine
    combine_kernel<<<Tt, 256>>>(out);
}

// round 5
// speedup vs baseline: 1.5260x; 1.0798x over previous
#include <cuda_runtime.h>
#include <cuda_bf16.h>
#include <mma.h>
#include <math.h>
#include <stdint.h>

using namespace nvcuda;

// ---------------- problem constants ----------------
#define Dm 1024      // d_model
#define Hd 4096      // expert hidden
#define Ex 8         // experts
#define TK 2         // top-k
#define Bb 4
#define Ss 2048
#define Tt (Bb * Ss)         // 8192 tokens
#define PAIRS (Tt * TK)      // 16384
#define CAP 2560             // ceil(1.25 * T * K / E)

// ---------------- device scratch (no allocations allowed) ----------------
__device__ float g_h  [(size_t)Ex * CAP * Hd];   // hidden acts (tf32-rounded)
__device__ float g_eo [(size_t)Ex * CAP * Dm];   // expert outputs (fp32)
__device__ float g_xr [(size_t)Tt * Dm];         // x rounded to tf32
__device__ float g_w1r[(size_t)Ex * Dm * Hd];    // W1 rounded to tf32
__device__ float g_w2r[(size_t)Ex * Hd * Dm];    // W2 rounded to tf32
__device__ int   g_eid[PAIRS];
__device__ float g_wp [PAIRS];
__device__ int   g_slot[PAIRS];
__device__ int   g_tok[Ex * CAP];
__device__ int   g_count[Ex];

// ---------------- helpers ----------------
__device__ __forceinline__ uint32_t smem_u32(const void* p) {
    uint32_t a;
    asm("{ .reg .u64 t; cvta.to.shared.u64 t, %1; cvt.u32.u64 %0, t; }" : "=r"(a) : "l"(p));
    return a;
}
__device__ __forceinline__ void cp16(uint32_t dst, const void* src) {
    asm volatile("cp.async.cg.shared.global [%0], [%1], 16;" :: "r"(dst), "l"(src));
}
#define CP_COMMIT() asm volatile("cp.async.commit_group;" ::: "memory")
#define CP_WAIT(n)  asm volatile("cp.async.wait_group %0;" :: "n"(n) : "memory")

__device__ __forceinline__ float round_tf32(float v) {
    float r;
    asm("cvt.rna.tf32.f32 %0, %1;" : "=f"(r) : "f"(v));
    return r;
}

// ---------------- router: warp per token ----------------
__global__ void router_kernel(const float* __restrict__ x,
                              const float* __restrict__ Wr)
{
    int warp = (blockIdx.x * blockDim.x + threadIdx.x) >> 5;
    int lane = threadIdx.x & 31;
    if (warp >= Tt) return;
    const float* xr = x + (size_t)warp * Dm;

    float acc[8];
#pragma unroll
    for (int e = 0; e < 8; e++) acc[e] = 0.f;
    for (int d = lane; d < Dm; d += 32) {
        float xv = __ldg(xr + d);
        const float4 a = *(const float4*)(Wr + d * 8);
        const float4 b = *(const float4*)(Wr + d * 8 + 4);
        acc[0] += xv * a.x; acc[1] += xv * a.y; acc[2] += xv * a.z; acc[3] += xv * a.w;
        acc[4] += xv * b.x; acc[5] += xv * b.y; acc[6] += xv * b.z; acc[7] += xv * b.w;
    }
#pragma unroll
    for (int e = 0; e < 8; e++)
#pragma unroll
        for (int off = 16; off > 0; off >>= 1)
            acc[e] += __shfl_xor_sync(0xFFFFFFFFu, acc[e], off);
    if (lane == 0) {
        int e0 = 0; float l0 = acc[0];
#pragma unroll
        for (int e = 1; e < 8; e++) if (acc[e] > l0) { l0 = acc[e]; e0 = e; }
        int e1 = -1; float l1 = -3.4e38f;
#pragma unroll
        for (int e = 0; e < 8; e++) {
            if (e == e0) continue;
            if (acc[e] > l1) { l1 = acc[e]; e1 = e; }
        }
        float w0 = 1.0f / (1.0f + __expf(l1 - l0));
        g_eid[2 * warp + 0] = e0;  g_eid[2 * warp + 1] = e1;
        g_wp [2 * warp + 0] = w0;  g_wp [2 * warp + 1] = 1.0f - w0;
    }
}

// ---------------- exact ordered capacity dispatch (single block) ----------------
__global__ void scan_kernel()
{
    __shared__ int sc[8][1024];
    int tid = threadIdx.x;
    int base = tid * 16;

    int le[16]; int lc[8];
#pragma unroll
    for (int e = 0; e < 8; e++) lc[e] = 0;
#pragma unroll
    for (int i = 0; i < 16; i++) { le[i] = g_eid[base + i]; lc[le[i]]++; }
#pragma unroll
    for (int e = 0; e < 8; e++) sc[e][tid] = lc[e];
    __syncthreads();
    for (int off = 1; off < 1024; off <<= 1) {
        int v[8];
#pragma unroll
        for (int e = 0; e < 8; e++) v[e] = (tid >= off) ? sc[e][tid - off] : 0;
        __syncthreads();
#pragma unroll
        for (int e = 0; e < 8; e++) sc[e][tid] += v[e];
        __syncthreads();
    }
    int pos[8];
#pragma unroll
    for (int e = 0; e < 8; e++) pos[e] = sc[e][tid] - lc[e];
#pragma unroll
    for (int i = 0; i < 16; i++) {
        int e = le[i]; int p = pos[e]++; int pr = base + i;
        if (p < CAP) { int s = e * CAP + p; g_slot[pr] = s; g_tok[s] = pr >> 1; }
        else g_slot[pr] = -1;
    }
    if (tid < 8) { int c = sc[tid][1023]; g_count[tid] = (c < CAP) ? c : CAP; }
}

// ---------------- elementwise tf32 rounding (one-shot) ----------------
__global__ void round_kernel(const float* __restrict__ src, float* __restrict__ dst,
                             size_t n4)
{
    size_t i = (size_t)blockIdx.x * blockDim.x + threadIdx.x;
    size_t stride = (size_t)gridDim.x * blockDim.x;
    for (; i < n4; i += stride) {
        float4 v = ((const float4*)src)[i];
        v.x = round_tf32(v.x); v.y = round_tf32(v.y);
        v.z = round_tf32(v.z); v.w = round_tf32(v.w);
        ((float4*)dst)[i] = v;
    }
}

// ---------------- GELU (tanh approx, matches jax.nn.gelu) ----------------
__device__ __forceinline__ float gelu_tanh(float v)
{
    float c = 0.7978845608028654f * (v + 0.044715f * v * v * v);
    return 0.5f * v * (1.0f + tanhf(c));
}

// ---------------- wmma tf32 expert GEMM (pre-rounded inputs, no cvt in loop) ----
// C[128x128] = act( A @ B + bias ),  A:[M][K] row-major (gathered), B:[K][N] row-major.
// 8 warps, warp tile 32x64; 16x16x8 tf32; BK=64, 3-stage cp.async, 1 sync/iter.
template <int Kdim, int Ndim, bool GELU, bool GATHER>
__global__ void __launch_bounds__(256)
expert_wmma(const float* __restrict__ Ax,
            const float* __restrict__ Bw,
            const float* __restrict__ bias)
{
    constexpr int BM = 128, BN = 128, BK = 64, NS = 3;
    constexpr int MT = CAP / BM;              // 20 row tiles / expert
    constexpr int AST = BK + 8;               // 72 floats (288 B)
    constexpr int BST = BN + 8;               // 136 floats (544 B)
    constexpr int ABYTES = BM * AST * 4;      // 36864
    constexpr int BBYTES = BK * BST * 4;      // 34816
    constexpr int STAGE  = ABYTES + BBYTES;   // 71680
    constexpr int CST = BN + 4;               // 528 B

    extern __shared__ __align__(16) char smem[];
    int*   srow = (int*)smem;                  // 512 B
    float* sC   = (float*)(smem + 512);        // reused after mainloop
    char*  stg  = smem + 512;
    const uint32_t stg_u = smem_u32(stg);

    const int e   = blockIdx.y / MT;
    const int m0  = (blockIdx.y % MT) * BM;
    const int cnt = g_count[e];
    if (m0 >= cnt) return;
    const int n0  = blockIdx.x * BN;
    const int tid = threadIdx.x;
    const int wid = tid >> 5;

    if (tid < BM) {
        int r = m0 + tid;
        srow[tid] = (r < cnt) ? (GATHER ? g_tok[e * CAP + r] : e * CAP + r)
                              : (GATHER ? 0 : e * CAP);
    }
    __syncthreads();

    const float* Asrc = GATHER ? Ax : (const float*)g_h;
    const float* Bexp = Bw + (size_t)e * Kdim * Ndim + n0;

    // A: 2048 16B chunks; chunk = tid + l*256; row = chunk>>4, c16 = chunk&15
    const int ar0 = tid >> 4, ac16 = tid & 15;
    int arows[8];
#pragma unroll
    for (int l = 0; l < 8; l++) arows[l] = srow[ar0 + l * 16];
    // B: 2048 chunks; row = chunk>>5, c16 = chunk&31
    const int br0 = tid >> 5, bc16 = tid & 31;

    auto load_stage = [&](int s, int k0) {
        uint32_t sA = stg_u + s * STAGE;
        uint32_t sB = sA + ABYTES;
#pragma unroll
        for (int l = 0; l < 8; l++) {
            int row = ar0 + l * 16;
            cp16(sA + (uint32_t)(row * (AST * 4) + ac16 * 16),
                 Asrc + (size_t)arows[l] * Kdim + k0 + ac16 * 4);
        }
#pragma unroll
        for (int l = 0; l < 8; l++) {
            int row = br0 + l * 8;
            cp16(sB + (uint32_t)(row * (BST * 4) + bc16 * 16),
                 Bexp + (size_t)(k0 + row) * Ndim + bc16 * 4);
        }
        CP_COMMIT();
    };

    const int warp_m = wid >> 1;     // 0..3
    const int warp_n = wid & 1;      // 0..1

    wmma::fragment<wmma::accumulator, 16, 16, 8, float> acc[2][4];
#pragma unroll
    for (int i = 0; i < 2; i++)
#pragma unroll
        for (int j = 0; j < 4; j++) wmma::fill_fragment(acc[i][j], 0.f);

    constexpr int KT = Kdim / BK;
    load_stage(0, 0);
    load_stage(1, BK);

    int cs = 0;                       // compute stage
    for (int j = 0; j < KT; j++) {
        if (j + 2 < KT) CP_WAIT(1); else CP_WAIT(0);
        __syncthreads();
        if (j + 2 < KT) {
            int ls = cs + 2; if (ls >= NS) ls -= NS;
            load_stage(ls, (j + 2) * BK);
        }

        const float* sA = (const float*)(stg + cs * STAGE);
        const float* sB = (const float*)(stg + cs * STAGE + ABYTES);

#pragma unroll
        for (int ks = 0; ks < BK / 8; ks++) {
            wmma::fragment<wmma::matrix_a, 16, 16, 8, wmma::precision::tf32, wmma::row_major> af[2];
            wmma::fragment<wmma::matrix_b, 16, 16, 8, wmma::precision::tf32, wmma::row_major> bf[4];
#pragma unroll
            for (int i = 0; i < 2; i++)
                wmma::load_matrix_sync(af[i], sA + (warp_m * 32 + i * 16) * AST + ks * 8, AST);
#pragma unroll
            for (int jn = 0; jn < 4; jn++)
                wmma::load_matrix_sync(bf[jn], sB + (ks * 8) * BST + warp_n * 64 + jn * 16, BST);
#pragma unroll
            for (int i = 0; i < 2; i++)
#pragma unroll
                for (int jn = 0; jn < 4; jn++)
                    wmma::mma_sync(acc[i][jn], af[i], bf[jn], acc[i][jn]);
        }
        cs++; if (cs >= NS) cs = 0;
    }

    __syncthreads();   // all warps done reading stages before sC overwrite

#pragma unroll
    for (int i = 0; i < 2; i++)
#pragma unroll
        for (int jn = 0; jn < 4; jn++)
            wmma::store_matrix_sync(sC + (warp_m * 32 + i * 16) * CST + warp_n * 64 + jn * 16,
                                    acc[i][jn], CST, wmma::mem_row_major);
    __syncthreads();

    // epilogue: 2 threads per row, 64 cols each
    {
        const int row  = tid >> 1;
        const int col0 = (tid & 1) * 64;
        const int r = m0 + row;
        if (r < cnt) {
            const float* bv = bias + e * Ndim + n0 + col0;
            float* crow = (GELU ? g_h : g_eo) + ((size_t)(e * CAP + r)) * Ndim + n0 + col0;
            const float* src = sC + row * CST + col0;
#pragma unroll
            for (int c = 0; c < 64; c += 4) {
                float4 v = *(const float4*)(src + c);
                v.x += __ldg(bv + c + 0);
                v.y += __ldg(bv + c + 1);
                v.z += __ldg(bv + c + 2);
                v.w += __ldg(bv + c + 3);
                if (GELU) {
                    // GELU then tf32-round so GEMM2 needs no in-loop conversion
                    v.x = round_tf32(gelu_tanh(v.x));
                    v.y = round_tf32(gelu_tanh(v.y));
                    v.z = round_tf32(gelu_tanh(v.z));
                    v.w = round_tf32(gelu_tanh(v.w));
                }
                *(float4*)(crow + c) = v;
            }
        }
    }
}

// ---------------- combine: one block per token ----------------
__global__ void combine_kernel(float* __restrict__ out)
{
    int t = blockIdx.x;
    int c = threadIdx.x * 4;
    int   s0 = g_slot[2 * t + 0];
    int   s1 = g_slot[2 * t + 1];
    float w0 = g_wp[2 * t + 0];
    float w1 = g_wp[2 * t + 1];
    float4 r = make_float4(0.f, 0.f, 0.f, 0.f);
    if (s0 >= 0) {
        float4 a = *(const float4*)(g_eo + (size_t)s0 * Dm + c);
        r.x += w0 * a.x; r.y += w0 * a.y; r.z += w0 * a.z; r.w += w0 * a.w;
    }
    if (s1 >= 0) {
        float4 a = *(const float4*)(g_eo + (size_t)s1 * Dm + c);
        r.x += w1 * a.x; r.y += w1 * a.y; r.z += w1 * a.z; r.w += w1 * a.w;
    }
    *(float4*)(out + (size_t)t * Dm + c) = r;
}

// ---------------- entry point ----------------
extern "C" void kernel_launch(void* const* d_in, const int* in_sizes, int n_in,
                              void* d_out, int out_size)
{
    const float* x  = (const float*)d_in[0];
    const float* Wr = (const float*)d_in[1];
    const float* W1 = (const float*)d_in[2];
    const float* b1 = (const float*)d_in[3];
    const float* W2 = (const float*)d_in[4];
    const float* b2 = (const float*)d_in[5];
    float* out = (float*)d_out;

    // dynamic smem: 512 + 3 * 71680 = 215552 B (~210.5 KB)
    constexpr int SMEM_SZ = 512 + 3 * 71680;
    cudaFuncSetAttribute((const void*)&expert_wmma<Dm, Hd, true,  true >,
                         cudaFuncAttributeMaxDynamicSharedMemorySize, SMEM_SZ);
    cudaFuncSetAttribute((const void*)&expert_wmma<Hd, Dm, false, false>,
                         cudaFuncAttributeMaxDynamicSharedMemorySize, SMEM_SZ);

    float* xr;  cudaGetSymbolAddress((void**)&xr,  g_xr);
    float* w1r; cudaGetSymbolAddress((void**)&w1r, g_w1r);
    float* w2r; cudaGetSymbolAddress((void**)&w2r, g_w2r);

    // 1) router (reads full-precision x)
    router_kernel<<<Tt / 8, 256>>>(x, Wr);
    // 2) exact ordered capacity dispatch
    scan_kernel<<<1, 1024>>>();
    // 2b) pre-round inputs/weights to tf32 (RN) once
    round_kernel<<<2048, 256>>>(x,  xr,  (size_t)Tt * Dm / 4);
    round_kernel<<<4096, 256>>>(W1, w1r, (size_t)Ex * Dm * Hd / 4);
    round_kernel<<<4096, 256>>>(W2, w2r, (size_t)Ex * Hd * Dm / 4);
    // 3) GEMM1 + GELU: xr[gather] @ W1r + b1 -> g_h (tf32-rounded)
    expert_wmma<Dm, Hd, true,  true ><<<dim3(Hd / 128, Ex * (CAP / 128)), 256, SMEM_SZ>>>(xr, w1r, b1);
    // 4) GEMM2: g_h @ W2r + b2 -> g_eo
    expert_wmma<Hd, Dm, false, false><<<dim3(Dm / 128, Ex * (CAP / 128)), 256, SMEM_SZ>>>(nullptr, w2r, b2);
    // 5) combine
    combine_kernel<<<Tt, 256>>>(out);
}

// round 6
// speedup vs baseline: 5.9253x; 3.8828x over previous
#include <cuda_runtime.h>
#include <cuda_fp16.h>
#include <mma.h>
#include <math.h>
#include <stdint.h>

using namespace nvcuda;

// ---------------- problem constants ----------------
#define Dm 1024      // d_model
#define Hd 4096      // expert hidden
#define Ex 8         // experts
#define TK 2         // top-k
#define Bb 4
#define Ss 2048
#define Tt (Bb * Ss)         // 8192 tokens
#define PAIRS (Tt * TK)      // 16384
#define CAP 2560             // ceil(1.25 * T * K / E)

// ---------------- device scratch (no allocations allowed) ----------------
__device__ __half g_h  [(size_t)Ex * CAP * Hd];   // hidden acts (fp16)
__device__ float  g_eo [(size_t)Ex * CAP * Dm];   // expert outputs (fp32)
__device__ __half g_xh [(size_t)Tt * Dm];         // x in fp16
__device__ __half g_w1h[(size_t)Ex * Dm * Hd];    // W1 in fp16
__device__ __half g_w2h[(size_t)Ex * Hd * Dm];    // W2 in fp16
__device__ int    g_eid[PAIRS];
__device__ float  g_wp [PAIRS];
__device__ int    g_slot[PAIRS];
__device__ int    g_tok[Ex * CAP];
__device__ int    g_count[Ex];

// ---------------- helpers ----------------
__device__ __forceinline__ uint32_t smem_u32(const void* p) {
    uint32_t a;
    asm("{ .reg .u64 t; cvta.to.shared.u64 t, %1; cvt.u32.u64 %0, t; }" : "=r"(a) : "l"(p));
    return a;
}
__device__ __forceinline__ void cp16(uint32_t dst, const void* src) {
    asm volatile("cp.async.cg.shared.global [%0], [%1], 16;" :: "r"(dst), "l"(src));
}
#define CP_COMMIT() asm volatile("cp.async.commit_group;" ::: "memory")
#define CP_WAIT(n)  asm volatile("cp.async.wait_group %0;" :: "n"(n) : "memory")

// ---------------- router: warp per token ----------------
__global__ void router_kernel(const float* __restrict__ x,
                              const float* __restrict__ Wr)
{
    int warp = (blockIdx.x * blockDim.x + threadIdx.x) >> 5;
    int lane = threadIdx.x & 31;
    if (warp >= Tt) return;
    const float* xr = x + (size_t)warp * Dm;

    float acc[8];
#pragma unroll
    for (int e = 0; e < 8; e++) acc[e] = 0.f;
    for (int d = lane; d < Dm; d += 32) {
        float xv = __ldg(xr + d);
        const float4 a = *(const float4*)(Wr + d * 8);
        const float4 b = *(const float4*)(Wr + d * 8 + 4);
        acc[0] += xv * a.x; acc[1] += xv * a.y; acc[2] += xv * a.z; acc[3] += xv * a.w;
        acc[4] += xv * b.x; acc[5] += xv * b.y; acc[6] += xv * b.z; acc[7] += xv * b.w;
    }
#pragma unroll
    for (int e = 0; e < 8; e++)
#pragma unroll
        for (int off = 16; off > 0; off >>= 1)
            acc[e] += __shfl_xor_sync(0xFFFFFFFFu, acc[e], off);
    if (lane == 0) {
        int e0 = 0; float l0 = acc[0];
#pragma unroll
        for (int e = 1; e < 8; e++) if (acc[e] > l0) { l0 = acc[e]; e0 = e; }
        int e1 = -1; float l1 = -3.4e38f;
#pragma unroll
        for (int e = 0; e < 8; e++) {
            if (e == e0) continue;
            if (acc[e] > l1) { l1 = acc[e]; e1 = e; }
        }
        float w0 = 1.0f / (1.0f + __expf(l1 - l0));
        g_eid[2 * warp + 0] = e0;  g_eid[2 * warp + 1] = e1;
        g_wp [2 * warp + 0] = w0;  g_wp [2 * warp + 1] = 1.0f - w0;
    }
}

// ---------------- exact ordered capacity dispatch (single block) ----------------
__global__ void scan_kernel()
{
    __shared__ int sc[8][1024];
    int tid = threadIdx.x;
    int base = tid * 16;

    int le[16]; int lc[8];
#pragma unroll
    for (int e = 0; e < 8; e++) lc[e] = 0;
#pragma unroll
    for (int i = 0; i < 16; i++) { le[i] = g_eid[base + i]; lc[le[i]]++; }
#pragma unroll
    for (int e = 0; e < 8; e++) sc[e][tid] = lc[e];
    __syncthreads();
    for (int off = 1; off < 1024; off <<= 1) {
        int v[8];
#pragma unroll
        for (int e = 0; e < 8; e++) v[e] = (tid >= off) ? sc[e][tid - off] : 0;
        __syncthreads();
#pragma unroll
        for (int e = 0; e < 8; e++) sc[e][tid] += v[e];
        __syncthreads();
    }
    int pos[8];
#pragma unroll
    for (int e = 0; e < 8; e++) pos[e] = sc[e][tid] - lc[e];
#pragma unroll
    for (int i = 0; i < 16; i++) {
        int e = le[i]; int p = pos[e]++; int pr = base + i;
        if (p < CAP) { int s = e * CAP + p; g_slot[pr] = s; g_tok[s] = pr >> 1; }
        else g_slot[pr] = -1;
    }
    if (tid < 8) { int c = sc[tid][1023]; g_count[tid] = (c < CAP) ? c : CAP; }
}

// ---------------- f32 -> f16 conversion (one-shot, vectorized x8) ----------------
__global__ void f2h_kernel(const float* __restrict__ src, __half* __restrict__ dst,
                           size_t n8)
{
    size_t i = (size_t)blockIdx.x * blockDim.x + threadIdx.x;
    size_t stride = (size_t)gridDim.x * blockDim.x;
    for (; i < n8; i += stride) {
        float4 a = ((const float4*)src)[2 * i + 0];
        float4 b = ((const float4*)src)[2 * i + 1];
        __half2 h[4];
        h[0] = __floats2half2_rn(a.x, a.y);
        h[1] = __floats2half2_rn(a.z, a.w);
        h[2] = __floats2half2_rn(b.x, b.y);
        h[3] = __floats2half2_rn(b.z, b.w);
        ((uint4*)dst)[i] = *(uint4*)h;
    }
}

// ---------------- GELU (tanh approx, matches jax.nn.gelu) ----------------
__device__ __forceinline__ float gelu_tanh(float v)
{
    float c = 0.7978845608028654f * (v + 0.044715f * v * v * v);
    return 0.5f * v * (1.0f + tanhf(c));
}

// ---------------- wmma fp16 expert GEMM ----------------
// C[128x128] = act( A @ B + bias ),  A:[M][K] fp16 row-major (gathered),
// B:[K][N] fp16 row-major. 8 warps, warp tile 32x64, wmma 16x16x16 half,
// fp32 accum, BK=64, 3-stage cp.async, 2 CTAs/SM.
template <int Kdim, int Ndim, bool GELU, bool GATHER>
__global__ void __launch_bounds__(256, 2)
expert_wmma(const __half* __restrict__ Ax,
            const __half* __restrict__ Bw,
            const float* __restrict__ bias)
{
    constexpr int BM = 128, BN = 128, BK = 64, NS = 3;
    constexpr int MT = CAP / BM;              // 20 row tiles / expert
    constexpr int ASTh = BK + 8;              // 72 halfs (144 B, 16B-mult)
    constexpr int BSTh = BN + 8;              // 136 halfs (272 B)
    constexpr int ABYTES = BM * ASTh * 2;     // 18432
    constexpr int BBYTES = BK * BSTh * 2;     // 17408
    constexpr int STAGE  = ABYTES + BBYTES;   // 35840
    constexpr int CST = BN + 4;               // C smem stride (floats)

    extern __shared__ __align__(16) char smem[];
    int*   srow = (int*)smem;                  // 512 B
    float* sC   = (float*)(smem + 512);        // reused after mainloop (67584 B)
    char*  stg  = smem + 512;
    const uint32_t stg_u = smem_u32(stg);

    const int e   = blockIdx.y / MT;
    const int m0  = (blockIdx.y % MT) * BM;
    const int cnt = g_count[e];
    if (m0 >= cnt) return;
    const int n0  = blockIdx.x * BN;
    const int tid = threadIdx.x;
    const int wid = tid >> 5;

    if (tid < BM) {
        int r = m0 + tid;
        srow[tid] = (r < cnt) ? (GATHER ? g_tok[e * CAP + r] : e * CAP + r)
                              : (GATHER ? 0 : e * CAP);
    }
    __syncthreads();

    const __half* Asrc = GATHER ? Ax : (const __half*)g_h;
    const __half* Bexp = Bw + (size_t)e * Kdim * Ndim + n0;

    // A: 128 rows x 64 halfs = 1024 x 16B chunks; row = chunk>>3, c8 = chunk&7
    const int ar0 = tid >> 3, ac8 = tid & 7;
    int arows[4];
#pragma unroll
    for (int l = 0; l < 4; l++) arows[l] = srow[ar0 + l * 32];
    // B: 64 rows x 128 halfs = 1024 chunks; row = chunk>>4, c8 = chunk&15
    const int br0 = tid >> 4, bc8 = tid & 15;

    auto load_stage = [&](int s, int k0) {
        uint32_t sA = stg_u + s * STAGE;
        uint32_t sB = sA + ABYTES;
#pragma unroll
        for (int l = 0; l < 4; l++) {
            int row = ar0 + l * 32;
            cp16(sA + (uint32_t)(row * (ASTh * 2) + ac8 * 16),
                 Asrc + (size_t)arows[l] * Kdim + k0 + ac8 * 8);
        }
#pragma unroll
        for (int l = 0; l < 4; l++) {
            int row = br0 + l * 16;
            cp16(sB + (uint32_t)(row * (BSTh * 2) + bc8 * 16),
                 Bexp + (size_t)(k0 + row) * Ndim + bc8 * 8);
        }
        CP_COMMIT();
    };

    const int warp_m = wid >> 1;     // 0..3
    const int warp_n = wid & 1;      // 0..1

    wmma::fragment<wmma::accumulator, 16, 16, 16, float> acc[2][4];
#pragma unroll
    for (int i = 0; i < 2; i++)
#pragma unroll
        for (int j = 0; j < 4; j++) wmma::fill_fragment(acc[i][j], 0.f);

    constexpr int KT = Kdim / BK;
    load_stage(0, 0);
    load_stage(1, BK);

    int cs = 0;
    for (int j = 0; j < KT; j++) {
        if (j + 2 < KT) CP_WAIT(1); else CP_WAIT(0);
        __syncthreads();
        if (j + 2 < KT) {
            int ls = cs + 2; if (ls >= NS) ls -= NS;
            load_stage(ls, (j + 2) * BK);
        }

        const __half* sA = (const __half*)(stg + cs * STAGE);
        const __half* sB = (const __half*)(stg + cs * STAGE + ABYTES);

#pragma unroll
        for (int ks = 0; ks < BK / 16; ks++) {
            wmma::fragment<wmma::matrix_a, 16, 16, 16, __half, wmma::row_major> af[2];
            wmma::fragment<wmma::matrix_b, 16, 16, 16, __half, wmma::row_major> bf[4];
#pragma unroll
            for (int i = 0; i < 2; i++)
                wmma::load_matrix_sync(af[i], sA + (warp_m * 32 + i * 16) * ASTh + ks * 16, ASTh);
#pragma unroll
            for (int jn = 0; jn < 4; jn++)
                wmma::load_matrix_sync(bf[jn], sB + (ks * 16) * BSTh + warp_n * 64 + jn * 16, BSTh);
#pragma unroll
            for (int i = 0; i < 2; i++)
#pragma unroll
                for (int jn = 0; jn < 4; jn++)
                    wmma::mma_sync(acc[i][jn], af[i], bf[jn], acc[i][jn]);
        }
        cs++; if (cs >= NS) cs = 0;
    }

    __syncthreads();   // all warps done with stages before sC overwrite

#pragma unroll
    for (int i = 0; i < 2; i++)
#pragma unroll
        for (int jn = 0; jn < 4; jn++)
            wmma::store_matrix_sync(sC + (warp_m * 32 + i * 16) * CST + warp_n * 64 + jn * 16,
                                    acc[i][jn], CST, wmma::mem_row_major);
    __syncthreads();

    // epilogue: 2 threads per row, 64 cols each
    {
        const int row  = tid >> 1;
        const int col0 = (tid & 1) * 64;
        const int r = m0 + row;
        if (r < cnt) {
            const float* bv = bias + e * Ndim + n0 + col0;
            const float* src = sC + row * CST + col0;
            if (GELU) {
                __half* crow = (__half*)g_h + ((size_t)(e * CAP + r)) * Ndim + n0 + col0;
#pragma unroll
                for (int c = 0; c < 64; c += 4) {
                    float4 v = *(const float4*)(src + c);
                    v.x = gelu_tanh(v.x + __ldg(bv + c + 0));
                    v.y = gelu_tanh(v.y + __ldg(bv + c + 1));
                    v.z = gelu_tanh(v.z + __ldg(bv + c + 2));
                    v.w = gelu_tanh(v.w + __ldg(bv + c + 3));
                    __half2 h0 = __floats2half2_rn(v.x, v.y);
                    __half2 h1 = __floats2half2_rn(v.z, v.w);
                    *(uint2*)(crow + c) = make_uint2(*(uint32_t*)&h0, *(uint32_t*)&h1);
                }
            } else {
                float* crow = g_eo + ((size_t)(e * CAP + r)) * Ndim + n0 + col0;
#pragma unroll
                for (int c = 0; c < 64; c += 4) {
                    float4 v = *(const float4*)(src + c);
                    v.x += __ldg(bv + c + 0);
                    v.y += __ldg(bv + c + 1);
                    v.z += __ldg(bv + c + 2);
                    v.w += __ldg(bv + c + 3);
                    *(float4*)(crow + c) = v;
                }
            }
        }
    }
}

// ---------------- combine: one block per token ----------------
__global__ void combine_kernel(float* __restrict__ out)
{
    int t = blockIdx.x;
    int c = threadIdx.x * 4;
    int   s0 = g_slot[2 * t + 0];
    int   s1 = g_slot[2 * t + 1];
    float w0 = g_wp[2 * t + 0];
    float w1 = g_wp[2 * t + 1];
    float4 r = make_float4(0.f, 0.f, 0.f, 0.f);
    if (s0 >= 0) {
        float4 a = *(const float4*)(g_eo + (size_t)s0 * Dm + c);
        r.x += w0 * a.x; r.y += w0 * a.y; r.z += w0 * a.z; r.w += w0 * a.w;
    }
    if (s1 >= 0) {
        float4 a = *(const float4*)(g_eo + (size_t)s1 * Dm + c);
        r.x += w1 * a.x; r.y += w1 * a.y; r.z += w1 * a.z; r.w += w1 * a.w;
    }
    *(float4*)(out + (size_t)t * Dm + c) = r;
}

// ---------------- entry point ----------------
extern "C" void kernel_launch(void* const* d_in, const int* in_sizes, int n_in,
                              void* d_out, int out_size)
{
    const float* x  = (const float*)d_in[0];
    const float* Wr = (const float*)d_in[1];
    const float* W1 = (const float*)d_in[2];
    const float* b1 = (const float*)d_in[3];
    const float* W2 = (const float*)d_in[4];
    const float* b2 = (const float*)d_in[5];
    float* out = (float*)d_out;

    // dynamic smem: 512 + 3 * 35840 = 108032 B (fits 2 CTAs/SM)
    constexpr int SMEM_SZ = 512 + 3 * 35840;
    static_assert(512 + 128 * (128 + 4) * 4 <= SMEM_SZ, "C reuse fits");
    cudaFuncSetAttribute((const void*)&expert_wmma<Dm, Hd, true,  true >,
                         cudaFuncAttributeMaxDynamicSharedMemorySize, SMEM_SZ);
    cudaFuncSetAttribute((const void*)&expert_wmma<Hd, Dm, false, false>,
                         cudaFuncAttributeMaxDynamicSharedMemorySize, SMEM_SZ);

    __half* xh;  cudaGetSymbolAddress((void**)&xh,  g_xh);
    __half* w1h; cudaGetSymbolAddress((void**)&w1h, g_w1h);
    __half* w2h; cudaGetSymbolAddress((void**)&w2h, g_w2h);

    // 1) router (full-precision x)
    router_kernel<<<Tt / 8, 256>>>(x, Wr);
    // 2) exact ordered capacity dispatch
    scan_kernel<<<1, 1024>>>();
    // 2b) one-shot fp32 -> fp16 conversions
    f2h_kernel<<<1024, 256>>>(x,  xh,  (size_t)Tt * Dm / 8);
    f2h_kernel<<<2048, 256>>>(W1, w1h, (size_t)Ex * Dm * Hd / 8);
    f2h_kernel<<<2048, 256>>>(W2, w2h, (size_t)Ex * Hd * Dm / 8);
    // 3) GEMM1 + GELU: xh[gather] @ W1h + b1 -> g_h (fp16)
    expert_wmma<Dm, Hd, true,  true ><<<dim3(Hd / 128, Ex * (CAP / 128)), 256, SMEM_SZ>>>(xh, w1h, b1);
    // 4) GEMM2: g_h @ W2h + b2 -> g_eo (fp32)
    expert_wmma<Hd, Dm, false, false><<<dim3(Dm / 128, Ex * (CAP / 128)), 256, SMEM_SZ>>>(nullptr, w2h, b2);
    // 5) combine
    combine_kernel<<<Tt, 256>>>(out);
}